// round 2
// baseline (speedup 1.0000x reference)
#include <cuda_runtime.h>
#include <cuda_bf16.h>
#include <cstdint>

// RMAC max-pool over 14 fixed regions of a (64, 37, 37, 512) fp32 tensor.
// Regions (x, y, w, h) for W=H=37, L=3 (computed from the reference grid):
//   r0 : (0,0,37,37)
//   r1-4 : 24x24 at x,y in {0,13}   (order: y outer, x inner)
//   r5-13: 18x18 at x,y in {0,9,19} (order: y outer, x inner)
// Column intervals used: I0=[0,37) I1=[0,24) I2=[13,37) I3=[0,18) I4=[9,27) I5=[19,37)
// Row ranges: r0:[0,37) r1,r2:[0,24) r3,r4:[13,37) r5-7:[0,18) r8-10:[9,27) r11-13:[19,37)

#define BATCH   64
#define HH      37
#define WW      37
#define NCH     512
#define NREG    14
#define NSLICE  4
#define CPB     128              // channels per block (= threads per block)
#define NCHUNK  (NCH / CPB)      // 4
#define BRC     (BATCH * NREG * NCH)   // 458752 elements per slice of partials

#define NEG_INF __int_as_float(0xff800000)

// Partial region maxes per row-slice: [slice][b][region][channel]  (~7.3 MB)
__device__ float g_part[NSLICE][BATCH][NREG][NCH];

__global__ __launch_bounds__(CPB) void rmac_partial_kernel(const float* __restrict__ x) {
    const int bid   = blockIdx.x;            // 0 .. 1023
    const int s     = bid & (NSLICE - 1);    // row slice
    const int chunk = (bid >> 2) & (NCHUNK - 1);
    const int b     = bid >> 4;              // batch
    const int c     = chunk * CPB + threadIdx.x;

    const int h0 = (s * HH) / NSLICE;
    const int h1 = ((s + 1) * HH) / NSLICE;

    float acc[NREG];
#pragma unroll
    for (int r = 0; r < NREG; ++r) acc[r] = NEG_INF;

    const float* base = x + ((size_t)b * HH * WW) * NCH + c;

    for (int h = h0; h < h1; ++h) {
        const float* row = base + (size_t)h * WW * NCH;

        float m0 = NEG_INF, m1 = NEG_INF, m2 = NEG_INF;
        float m3 = NEG_INF, m4 = NEG_INF, m5 = NEG_INF;

        // Fully unrolled: all interval predicates are compile-time constants.
#pragma unroll
        for (int w = 0; w < WW; ++w) {
            const float v = __ldcs(row + (size_t)w * NCH);   // streaming: read-once data
            m0 = fmaxf(m0, v);                                // [0,37)
            if (w < 24)            m1 = fmaxf(m1, v);         // [0,24)
            if (w >= 13)           m2 = fmaxf(m2, v);         // [13,37)
            if (w < 18)            m3 = fmaxf(m3, v);         // [0,18)
            if (w >= 9 && w < 27)  m4 = fmaxf(m4, v);         // [9,27)
            if (w >= 19)           m5 = fmaxf(m5, v);         // [19,37)
        }

        // Fold row maxes into region accumulators (runtime predicates on h).
        acc[0] = fmaxf(acc[0], m0);
        const bool pA = (h < 24);               // rows [0,24)
        const bool pB = (h >= 13);              // rows [13,37)
        const bool pC = (h < 18);               // rows [0,18)
        const bool pD = (h >= 9 && h < 27);     // rows [9,27)
        const bool pE = (h >= 19);              // rows [19,37)
        if (pA) { acc[1]  = fmaxf(acc[1],  m1); acc[2]  = fmaxf(acc[2],  m2); }
        if (pB) { acc[3]  = fmaxf(acc[3],  m1); acc[4]  = fmaxf(acc[4],  m2); }
        if (pC) { acc[5]  = fmaxf(acc[5],  m3); acc[6]  = fmaxf(acc[6],  m4); acc[7]  = fmaxf(acc[7],  m5); }
        if (pD) { acc[8]  = fmaxf(acc[8],  m3); acc[9]  = fmaxf(acc[9],  m4); acc[10] = fmaxf(acc[10], m5); }
        if (pE) { acc[11] = fmaxf(acc[11], m3); acc[12] = fmaxf(acc[12], m4); acc[13] = fmaxf(acc[13], m5); }
    }

#pragma unroll
    for (int r = 0; r < NREG; ++r)
        g_part[s][b][r][c] = acc[r];
}

__global__ __launch_bounds__(512) void rmac_reduce_kernel(float* __restrict__ out) {
    const int i = blockIdx.x * blockDim.x + threadIdx.x;   // linear over [b][r][c]
    if (i >= BRC) return;
    const float* gp = &g_part[0][0][0][0];
    const float v01 = fmaxf(gp[i],           gp[i + BRC]);
    const float v23 = fmaxf(gp[i + 2 * BRC], gp[i + 3 * BRC]);
    out[i] = fmaxf(v01, v23);
}

extern "C" void kernel_launch(void* const* d_in, const int* in_sizes, int n_in,
                              void* d_out, int out_size) {
    const float* x = (const float*)d_in[0];
    float* out = (float*)d_out;

    rmac_partial_kernel<<<BATCH * NCHUNK * NSLICE, CPB>>>(x);
    rmac_reduce_kernel<<<(BRC + 511) / 512, 512>>>(out);
}

// round 3
// speedup vs baseline: 1.0181x; 1.0181x over previous
#include <cuda_runtime.h>
#include <cuda_bf16.h>
#include <cstdint>

// RMAC max-pool over 14 fixed regions of a (64, 37, 37, 512) fp32 tensor.
// Regions for W=H=37, L=3:
//   r0 : (0,0,37,37)
//   r1-4 : 24x24 at (x,y) in {0,13}^2   (y outer, x inner)
//   r5-13: 18x18 at (x,y) in {0,9,19}^2 (y outer, x inner)
// Column intervals: m0=[0,37) m1=[0,24) m2=[13,37) m3=[0,18) m4=[9,27) m5=[19,37)
// built from disjoint segments S1=[0,9) S2=[9,13) S3=[13,18) S4=[18,19)
//                              S5=[19,24) S6=[24,27) S7=[27,37)

#define BATCH   64
#define HH      37
#define WW      37
#define NCH     512
#define NREG    14
#define NSLICE  4
#define CPB     128              // channels per block (= threads per block)
#define NCHUNK  (NCH / CPB)      // 4
#define BRC     (BATCH * NREG * NCH)   // 458752 = output element count

#define NEG_INF __int_as_float(0xff800000)

// Encoded (order-preserving int) region maxes: [b][region][channel]
__device__ int g_enc[BRC];

// Order-preserving float->int encoding: a < b  <=>  enc(a) < enc(b) (signed).
__device__ __forceinline__ int enc_f(float f) {
    int i = __float_as_int(f);
    return (i >= 0) ? i : (i ^ 0x7fffffff);
}
__device__ __forceinline__ float dec_f(int e) {
    return __int_as_float((e >= 0) ? e : (e ^ 0x7fffffff));
}

__global__ __launch_bounds__(512) void rmac_init_kernel() {
    const int i = blockIdx.x * blockDim.x + threadIdx.x;
    if (i < BRC) g_enc[i] = 0x80000000;   // INT_MIN <= enc(any float)
}

__global__ __launch_bounds__(CPB) void rmac_partial_kernel(const float* __restrict__ x) {
    const int bid   = blockIdx.x;            // 0 .. 1023
    const int s     = bid & (NSLICE - 1);    // row slice
    const int chunk = (bid >> 2) & (NCHUNK - 1);
    const int b     = bid >> 4;              // batch
    const int c     = chunk * CPB + threadIdx.x;

    const int h0 = (s * HH) / NSLICE;
    const int h1 = ((s + 1) * HH) / NSLICE;

    float acc[NREG];
#pragma unroll
    for (int r = 0; r < NREG; ++r) acc[r] = NEG_INF;

    const float* base = x + ((size_t)b * HH * WW) * NCH + c;

    for (int h = h0; h < h1; ++h) {
        const float* row = base + (size_t)h * WW * NCH;
#define LDW(w) __ldcs(row + (w) * NCH)

        // 7 disjoint segment maxes (30 fmax, 37 streaming LDG)
        float s1 = LDW(0);
#pragma unroll
        for (int w = 1; w < 9; ++w)   s1 = fmaxf(s1, LDW(w));
        float s2 = LDW(9);
#pragma unroll
        for (int w = 10; w < 13; ++w) s2 = fmaxf(s2, LDW(w));
        float s3 = LDW(13);
#pragma unroll
        for (int w = 14; w < 18; ++w) s3 = fmaxf(s3, LDW(w));
        float s4 = LDW(18);
        float s5 = LDW(19);
#pragma unroll
        for (int w = 20; w < 24; ++w) s5 = fmaxf(s5, LDW(w));
        float s6 = LDW(24);
#pragma unroll
        for (int w = 25; w < 27; ++w) s6 = fmaxf(s6, LDW(w));
        float s7 = LDW(27);
#pragma unroll
        for (int w = 28; w < 37; ++w) s7 = fmaxf(s7, LDW(w));
#undef LDW

        // Combine segments into the 6 column-interval maxes (13 fmax)
        const float m3  = fmaxf(fmaxf(s1, s2), s3);        // [0,18)
        const float m1  = fmaxf(fmaxf(m3, s4), s5);        // [0,24)
        const float m0  = fmaxf(fmaxf(m1, s6), s7);        // [0,37)
        const float s56 = fmaxf(s5, s6);
        const float m5  = fmaxf(s56, s7);                  // [19,37)
        const float m4  = fmaxf(fmaxf(fmaxf(s2, s3), s4), s56); // [9,27)
        const float m2  = fmaxf(fmaxf(s3, s4), m5);        // [13,37)

        // Fold row maxes into region accumulators (runtime predicates on h).
        acc[0] = fmaxf(acc[0], m0);
        const bool pA = (h < 24);               // rows [0,24)
        const bool pB = (h >= 13);              // rows [13,37)
        const bool pC = (h < 18);               // rows [0,18)
        const bool pD = (h >= 9 && h < 27);     // rows [9,27)
        const bool pE = (h >= 19);              // rows [19,37)
        if (pA) { acc[1]  = fmaxf(acc[1],  m1); acc[2]  = fmaxf(acc[2],  m2); }
        if (pB) { acc[3]  = fmaxf(acc[3],  m1); acc[4]  = fmaxf(acc[4],  m2); }
        if (pC) { acc[5]  = fmaxf(acc[5],  m3); acc[6]  = fmaxf(acc[6],  m4); acc[7]  = fmaxf(acc[7],  m5); }
        if (pD) { acc[8]  = fmaxf(acc[8],  m3); acc[9]  = fmaxf(acc[9],  m4); acc[10] = fmaxf(acc[10], m5); }
        if (pE) { acc[11] = fmaxf(acc[11], m3); acc[12] = fmaxf(acc[12], m4); acc[13] = fmaxf(acc[13], m5); }
    }

    // Fold this slice's result into the global encoded max (REDG, no return).
    int* dst = &g_enc[((b * NREG) * NCH) + c];
#pragma unroll
    for (int r = 0; r < NREG; ++r)
        atomicMax(dst + r * NCH, enc_f(acc[r]));
}

__global__ __launch_bounds__(512) void rmac_decode_kernel(float* __restrict__ out) {
    const int i = blockIdx.x * blockDim.x + threadIdx.x;
    if (i < BRC) out[i] = dec_f(g_enc[i]);
}

extern "C" void kernel_launch(void* const* d_in, const int* in_sizes, int n_in,
                              void* d_out, int out_size) {
    const float* x = (const float*)d_in[0];
    float* out = (float*)d_out;

    rmac_init_kernel<<<(BRC + 511) / 512, 512>>>();
    rmac_partial_kernel<<<BATCH * NCHUNK * NSLICE, CPB>>>(x);
    rmac_decode_kernel<<<(BRC + 511) / 512, 512>>>(out);
}